// round 3
// baseline (speedup 1.0000x reference)
#include <cuda_runtime.h>

#define B_SZ   2
#define SEQ    2048
#define DM     2048
#define NH     32
#define NKV    8
#define HD     64
#define NREP   4
#define NT     (B_SZ * SEQ)   // 4096 tokens

// ---------------- scratch (static device globals; no runtime allocation) ----
__device__ float g_q[(size_t)NT * DM];          // 32 MB  [tok][h*64+d]
__device__ float g_k[(size_t)NT * NKV * HD];    //  8 MB
__device__ float g_v[(size_t)NT * NKV * HD];    //  8 MB
__device__ float g_o[(size_t)NT * DM];          // 32 MB

// ---------------- C[M,N] = A[M,K] * B[N,K]^T  (both row-major) --------------
// 64x64 tile, BK=16, 256 threads, 4x4 accumulators per thread.
__global__ void sgemm_nt(const float* __restrict__ A, const float* __restrict__ Bm,
                         float* __restrict__ C, int M, int N, int K) {
    __shared__ float As[16][64];
    __shared__ float Bs[16][64];
    const int tid = threadIdx.x;
    const int tx = tid & 15;
    const int ty = tid >> 4;
    const int n0 = blockIdx.x * 64;
    const int m0 = blockIdx.y * 64;
    const int lr = tid >> 2;          // 0..63 tile row
    const int lc = (tid & 3) << 2;    // 0,4,8,12 within k-tile

    const float* Ap = A  + (size_t)(m0 + lr) * K + lc;
    const float* Bp = Bm + (size_t)(n0 + lr) * K + lc;

    float acc[4][4];
#pragma unroll
    for (int i = 0; i < 4; i++)
#pragma unroll
        for (int j = 0; j < 4; j++) acc[i][j] = 0.f;

    for (int k0 = 0; k0 < K; k0 += 16) {
        float4 av = *reinterpret_cast<const float4*>(Ap + k0);
        float4 bv = *reinterpret_cast<const float4*>(Bp + k0);
        __syncthreads();
        As[lc + 0][lr] = av.x; As[lc + 1][lr] = av.y;
        As[lc + 2][lr] = av.z; As[lc + 3][lr] = av.w;
        Bs[lc + 0][lr] = bv.x; Bs[lc + 1][lr] = bv.y;
        Bs[lc + 2][lr] = bv.z; Bs[lc + 3][lr] = bv.w;
        __syncthreads();
#pragma unroll
        for (int kk = 0; kk < 16; kk++) {
            float4 a4 = *reinterpret_cast<const float4*>(&As[kk][ty * 4]);
            float4 b4 = *reinterpret_cast<const float4*>(&Bs[kk][tx * 4]);
            float ar[4] = {a4.x, a4.y, a4.z, a4.w};
            float br[4] = {b4.x, b4.y, b4.z, b4.w};
#pragma unroll
            for (int i = 0; i < 4; i++)
#pragma unroll
                for (int j = 0; j < 4; j++)
                    acc[i][j] += ar[i] * br[j];
        }
    }
#pragma unroll
    for (int i = 0; i < 4; i++) {
        float4 o = make_float4(acc[i][0], acc[i][1], acc[i][2], acc[i][3]);
        *reinterpret_cast<float4*>(C + (size_t)(m0 + ty * 4 + i) * N + n0 + tx * 4) = o;
    }
}

// ---------------- RoPE (in place) -------------------------------------------
// buf layout [B*S][nheads*64]; pair (d, d+32), angle = s * 10000^(-d/32)
__global__ void rope_kernel(float* __restrict__ buf, int nheads, int total) {
    int idx = blockIdx.x * blockDim.x + threadIdx.x;
    if (idx >= total) return;
    int d   = idx & 31;
    int h   = (idx >> 5) % nheads;
    int row = idx / (32 * nheads);
    int s   = row & (SEQ - 1);
    // ln(10000) = 9.210340371976184
    float inv = expf(-(float)d * (9.210340371976184f / 32.0f));
    float ang = (float)s * inv;
    float c  = cosf(ang);
    float si = sinf(ang);
    float* p = buf + (size_t)row * (nheads * HD) + h * HD;
    float x1 = p[d];
    float x2 = p[d + 32];
    p[d]      = x1 * c - x2 * si;
    p[d + 32] = x2 * c + x1 * si;
}

// ---------------- causal GQA flash attention --------------------------------
// grid (S/64, B*NH), 64 threads. One query row per thread.
// Online softmax over 32-key tiles; q + accumulator in registers.
__global__ void __launch_bounds__(64)
attn_kernel(const float* __restrict__ Q, const float* __restrict__ K,
            const float* __restrict__ V, float* __restrict__ O) {
    const int qb  = blockIdx.x;
    const int bh  = blockIdx.y;
    const int b   = bh >> 5;   // / NH
    const int h   = bh & 31;
    const int kvh = h >> 2;    // / NREP
    const int tid = threadIdx.x;
    const int qrow = qb * 64 + tid;

    __shared__ float Ks[32][64];
    __shared__ float Vs[32][64];
    __shared__ float Ss[32][64];   // [key][thread] -> conflict-free

    float qv[64];
    const float* qp = Q + ((size_t)(b * SEQ + qrow)) * DM + h * HD;
#pragma unroll
    for (int i = 0; i < 16; i++) {
        float4 t = reinterpret_cast<const float4*>(qp)[i];
        qv[4 * i] = t.x; qv[4 * i + 1] = t.y; qv[4 * i + 2] = t.z; qv[4 * i + 3] = t.w;
    }
    float acc[64];
#pragma unroll
    for (int i = 0; i < 64; i++) acc[i] = 0.f;
    float m = -1e30f, l = 0.f;

    const int nkb = qb * 2 + 2;   // key tiles of 32 covering keys <= qb*64+63
    for (int kb = 0; kb < nkb; kb++) {
        const int kr0 = kb * 32;
        __syncthreads();
        // cooperative load of K/V tiles: 512 float4 per tile, 64 threads
#pragma unroll
        for (int t = 0; t < 8; t++) {
            int e = tid + t * 64;
            int r = e >> 4;
            int c = (e & 15) << 2;
            size_t goff = ((size_t)(b * SEQ + kr0 + r)) * (NKV * HD) + kvh * HD + c;
            *reinterpret_cast<float4*>(&Ks[r][c]) = *reinterpret_cast<const float4*>(K + goff);
            *reinterpret_cast<float4*>(&Vs[r][c]) = *reinterpret_cast<const float4*>(V + goff);
        }
        __syncthreads();

        float bm = -1e30f;
#pragma unroll 4
        for (int kk = 0; kk < 32; kk++) {
            const float4* kr = reinterpret_cast<const float4*>(&Ks[kk][0]);
            float s = 0.f;
#pragma unroll
            for (int d = 0; d < 16; d++) {
                float4 kw = kr[d];
                s += qv[4 * d] * kw.x + qv[4 * d + 1] * kw.y
                   + qv[4 * d + 2] * kw.z + qv[4 * d + 3] * kw.w;
            }
            s *= 0.125f;                       // 1/sqrt(64)
            if (kr0 + kk > qrow) s = -1e30f;   // causal mask (matches -1e9 additive)
            Ss[kk][tid] = s;
            bm = fmaxf(bm, s);
        }

        float mnew = fmaxf(m, bm);
        float corr = expf(m - mnew);
        l *= corr;
#pragma unroll
        for (int d = 0; d < 64; d++) acc[d] *= corr;

#pragma unroll 2
        for (int kk = 0; kk < 32; kk++) {
            float p = expf(Ss[kk][tid] - mnew);
            l += p;
            const float4* vr = reinterpret_cast<const float4*>(&Vs[kk][0]);
#pragma unroll
            for (int d = 0; d < 16; d++) {
                float4 vw = vr[d];
                acc[4 * d]     += p * vw.x;
                acc[4 * d + 1] += p * vw.y;
                acc[4 * d + 2] += p * vw.z;
                acc[4 * d + 3] += p * vw.w;
            }
        }
        m = mnew;
    }

    float invl = 1.0f / l;
    float* op = O + ((size_t)(b * SEQ + qrow)) * DM + h * HD;
#pragma unroll
    for (int i = 0; i < 16; i++) {
        float4 t = make_float4(acc[4 * i] * invl, acc[4 * i + 1] * invl,
                               acc[4 * i + 2] * invl, acc[4 * i + 3] * invl);
        reinterpret_cast<float4*>(op)[i] = t;
    }
}

// ---------------- launch ----------------------------------------------------
extern "C" void kernel_launch(void* const* d_in, const int* in_sizes, int n_in,
                              void* d_out, int out_size) {
    const float* x  = (const float*)d_in[0];
    const float* Wq = (const float*)d_in[1];
    const float* Wk = (const float*)d_in[2];
    const float* Wv = (const float*)d_in[3];
    const float* Wo = (const float*)d_in[4];
    // d_in[5] = precomputed causal mask; causality is applied analytically.
    float* out = (float*)d_out;

    float *gq, *gk, *gv, *go;
    cudaGetSymbolAddress((void**)&gq, g_q);
    cudaGetSymbolAddress((void**)&gk, g_k);
    cudaGetSymbolAddress((void**)&gv, g_v);
    cudaGetSymbolAddress((void**)&go, g_o);

    // projections: q = x Wq^T, k = x Wk^T, v = x Wv^T
    sgemm_nt<<<dim3(DM / 64, NT / 64), 256>>>(x, Wq, gq, NT, DM, DM);
    sgemm_nt<<<dim3((NKV * HD) / 64, NT / 64), 256>>>(x, Wk, gk, NT, NKV * HD, DM);
    sgemm_nt<<<dim3((NKV * HD) / 64, NT / 64), 256>>>(x, Wv, gv, NT, NKV * HD, DM);

    // RoPE on q and k
    int tq = NT * NH * 32;
    rope_kernel<<<(tq + 255) / 256, 256>>>(gq, NH, tq);
    int tk = NT * NKV * 32;
    rope_kernel<<<(tk + 255) / 256, 256>>>(gk, NKV, tk);

    // causal GQA attention
    attn_kernel<<<dim3(SEQ / 64, B_SZ * NH), 64>>>(gq, gk, gv, go);

    // output projection into d_out
    sgemm_nt<<<dim3(DM / 64, NT / 64), 256>>>(go, Wo, out, NT, DM, DM);
}

// round 5
// speedup vs baseline: 2.8759x; 2.8759x over previous
#include <cuda_runtime.h>
#include <cstdint>

#define B_SZ   2
#define SEQ    2048
#define DM     2048
#define NH     32
#define NKV    8
#define HD     64
#define NT     (B_SZ * SEQ)   // 4096 tokens

// ---------------- scratch (static device globals; no runtime allocation) ----
__device__ float g_q[(size_t)NT * DM];          // 32 MB
__device__ float g_k[(size_t)NT * NKV * HD];    //  8 MB
__device__ float g_v[(size_t)NT * NKV * HD];    //  8 MB
__device__ float g_o[(size_t)NT * DM];          // 32 MB

__device__ __forceinline__ float to_tf32(float x) {
    asm("cvt.rna.tf32.f32 %0, %1;" : "=f"(x) : "f"(x));
    return x;
}

// ============ tf32 tensor GEMM: C[M,N] = A[M,K] * B[N,K]^T (row-major) ======
// CTA tile 128x128, BK=32, 256 threads (8 warps, 4 along M x 2 along N).
// Warp tile 32x64 = 2 (m16) x 8 (n8) mma.m16n8k8 fragments.
// Smem: double-buffered A/B tiles as [128][36] fp32 (pad 4 -> conflict-free
// fragment loads: lane bank = g*4 + tig covers all 32 banks).
#define BK 32
#define LDS_PAD 36
#define TILE_F (128 * LDS_PAD)                 // floats per tile buffer
#define GEMM_SMEM (4 * TILE_F * 4)             // 2 bufs x (A+B) = 73728 B

__global__ void __launch_bounds__(256, 1)
gemm_tf32(const float* __restrict__ A, const float* __restrict__ Bm,
          float* __restrict__ C, int N, int K) {
    extern __shared__ float smem[];
    const int tid = threadIdx.x;
    const int wid = tid >> 5;
    const int lane = tid & 31;
    const int g   = lane >> 2;     // groupID 0..7
    const int tig = lane & 3;      // thread-in-group 0..3
    const int wm0 = (wid & 3) * 32;
    const int wn0 = (wid >> 2) * 64;
    const int n0 = blockIdx.x * 128;
    const int m0 = blockIdx.y * 128;

    // gmem load mapping: element e in [0,1024): row = e>>3, 16B col = e&7
    const int lr = tid >> 3;          // rows handled: lr, (4 rows/warp-step)
    const int lc = (tid & 7) * 4;     // float col

    float acc[2][8][4];
#pragma unroll
    for (int mt = 0; mt < 2; mt++)
#pragma unroll
        for (int nt = 0; nt < 8; nt++)
#pragma unroll
            for (int r = 0; r < 4; r++) acc[mt][nt][r] = 0.f;

    const int NITER = K / BK;
    float4 pa[4], pb[4];

    // prime: load tile 0
#pragma unroll
    for (int t = 0; t < 4; t++) {
        int r = lr + t * 32;
        pa[t] = *reinterpret_cast<const float4*>(A  + (size_t)(m0 + r) * K + lc);
        pb[t] = *reinterpret_cast<const float4*>(Bm + (size_t)(n0 + r) * K + lc);
    }
    {
        float* As = smem;
        float* Bs = smem + TILE_F;
#pragma unroll
        for (int t = 0; t < 4; t++) {
            int r = lr + t * 32;
            float4 a = pa[t], b = pb[t];
            a.x = to_tf32(a.x); a.y = to_tf32(a.y); a.z = to_tf32(a.z); a.w = to_tf32(a.w);
            b.x = to_tf32(b.x); b.y = to_tf32(b.y); b.z = to_tf32(b.z); b.w = to_tf32(b.w);
            *reinterpret_cast<float4*>(&As[r * LDS_PAD + lc]) = a;
            *reinterpret_cast<float4*>(&Bs[r * LDS_PAD + lc]) = b;
        }
    }
    __syncthreads();

    for (int i = 0; i < NITER; i++) {
        // prefetch next tile
        if (i + 1 < NITER) {
            const int k0 = (i + 1) * BK;
#pragma unroll
            for (int t = 0; t < 4; t++) {
                int r = lr + t * 32;
                pa[t] = *reinterpret_cast<const float4*>(A  + (size_t)(m0 + r) * K + k0 + lc);
                pb[t] = *reinterpret_cast<const float4*>(Bm + (size_t)(n0 + r) * K + k0 + lc);
            }
        }

        const float* As = smem + (i & 1) * 2 * TILE_F;
        const float* Bs = As + TILE_F;
#pragma unroll
        for (int ks = 0; ks < 4; ks++) {
            const int k = ks * 8;
            uint32_t af[2][4], bf[8][2];
#pragma unroll
            for (int mt = 0; mt < 2; mt++) {
                const int am = wm0 + mt * 16 + g;
                af[mt][0] = __float_as_uint(As[(am)     * LDS_PAD + k + tig]);
                af[mt][1] = __float_as_uint(As[(am + 8) * LDS_PAD + k + tig]);
                af[mt][2] = __float_as_uint(As[(am)     * LDS_PAD + k + tig + 4]);
                af[mt][3] = __float_as_uint(As[(am + 8) * LDS_PAD + k + tig + 4]);
            }
#pragma unroll
            for (int nt = 0; nt < 8; nt++) {
                const int bn = wn0 + nt * 8 + g;
                bf[nt][0] = __float_as_uint(Bs[bn * LDS_PAD + k + tig]);
                bf[nt][1] = __float_as_uint(Bs[bn * LDS_PAD + k + tig + 4]);
            }
#pragma unroll
            for (int mt = 0; mt < 2; mt++)
#pragma unroll
                for (int nt = 0; nt < 8; nt++) {
                    float* c = acc[mt][nt];
                    asm volatile(
                        "mma.sync.aligned.m16n8k8.row.col.f32.tf32.tf32.f32 "
                        "{%0,%1,%2,%3}, {%4,%5,%6,%7}, {%8,%9}, {%0,%1,%2,%3};"
                        : "+f"(c[0]), "+f"(c[1]), "+f"(c[2]), "+f"(c[3])
                        : "r"(af[mt][0]), "r"(af[mt][1]), "r"(af[mt][2]), "r"(af[mt][3]),
                          "r"(bf[nt][0]), "r"(bf[nt][1]));
                }
        }

        // store next tile into other buffer
        if (i + 1 < NITER) {
            float* Asn = smem + ((i + 1) & 1) * 2 * TILE_F;
            float* Bsn = Asn + TILE_F;
#pragma unroll
            for (int t = 0; t < 4; t++) {
                int r = lr + t * 32;
                float4 a = pa[t], b = pb[t];
                a.x = to_tf32(a.x); a.y = to_tf32(a.y); a.z = to_tf32(a.z); a.w = to_tf32(a.w);
                b.x = to_tf32(b.x); b.y = to_tf32(b.y); b.z = to_tf32(b.z); b.w = to_tf32(b.w);
                *reinterpret_cast<float4*>(&Asn[r * LDS_PAD + lc]) = a;
                *reinterpret_cast<float4*>(&Bsn[r * LDS_PAD + lc]) = b;
            }
            __syncthreads();
        }
    }

    // epilogue: c0,c1 -> (row, col..col+1); c2,c3 -> (row+8, ...)
#pragma unroll
    for (int mt = 0; mt < 2; mt++) {
        const int row = m0 + wm0 + mt * 16 + g;
#pragma unroll
        for (int nt = 0; nt < 8; nt++) {
            const int col = n0 + wn0 + nt * 8 + tig * 2;
            const float* c = acc[mt][nt];
            *reinterpret_cast<float2*>(C + (size_t)row * N + col) =
                make_float2(c[0], c[1]);
            *reinterpret_cast<float2*>(C + (size_t)(row + 8) * N + col) =
                make_float2(c[2], c[3]);
        }
    }
}

// ---------------- RoPE (in place) -------------------------------------------
__global__ void rope_kernel(float* __restrict__ buf, int nheads, int total) {
    int idx = blockIdx.x * blockDim.x + threadIdx.x;
    if (idx >= total) return;
    int d   = idx & 31;
    int h   = (idx >> 5) % nheads;
    int row = idx / (32 * nheads);
    int s   = row & (SEQ - 1);
    float inv = expf(-(float)d * (9.210340371976184f / 32.0f));
    float ang = (float)s * inv;
    float c  = cosf(ang);
    float si = sinf(ang);
    float* p = buf + (size_t)row * (nheads * HD) + h * HD;
    float x1 = p[d];
    float x2 = p[d + 32];
    p[d]      = x1 * c - x2 * si;
    p[d + 32] = x2 * c + x1 * si;
}

// ---------------- causal GQA flash attention (fp32) --------------------------
__global__ void __launch_bounds__(64)
attn_kernel(const float* __restrict__ Q, const float* __restrict__ K,
            const float* __restrict__ V, float* __restrict__ O) {
    const int qb  = blockIdx.x;
    const int bh  = blockIdx.y;
    const int b   = bh >> 5;
    const int h   = bh & 31;
    const int kvh = h >> 2;
    const int tid = threadIdx.x;
    const int qrow = qb * 64 + tid;

    __shared__ float Ks[32][64];
    __shared__ float Vs[32][64];
    __shared__ float Ss[32][64];

    float qv[64];
    const float* qp = Q + ((size_t)(b * SEQ + qrow)) * DM + h * HD;
#pragma unroll
    for (int i = 0; i < 16; i++) {
        float4 t = reinterpret_cast<const float4*>(qp)[i];
        qv[4 * i] = t.x; qv[4 * i + 1] = t.y; qv[4 * i + 2] = t.z; qv[4 * i + 3] = t.w;
    }
    float acc[64];
#pragma unroll
    for (int i = 0; i < 64; i++) acc[i] = 0.f;
    float m = -1e30f, l = 0.f;

    const int nkb = qb * 2 + 2;
    for (int kb = 0; kb < nkb; kb++) {
        const int kr0 = kb * 32;
        __syncthreads();
#pragma unroll
        for (int t = 0; t < 8; t++) {
            int e = tid + t * 64;
            int r = e >> 4;
            int c = (e & 15) << 2;
            size_t goff = ((size_t)(b * SEQ + kr0 + r)) * (NKV * HD) + kvh * HD + c;
            *reinterpret_cast<float4*>(&Ks[r][c]) = *reinterpret_cast<const float4*>(K + goff);
            *reinterpret_cast<float4*>(&Vs[r][c]) = *reinterpret_cast<const float4*>(V + goff);
        }
        __syncthreads();

        float bm = -1e30f;
#pragma unroll 4
        for (int kk = 0; kk < 32; kk++) {
            const float4* kr = reinterpret_cast<const float4*>(&Ks[kk][0]);
            float s = 0.f;
#pragma unroll
            for (int d = 0; d < 16; d++) {
                float4 kw = kr[d];
                s += qv[4 * d] * kw.x + qv[4 * d + 1] * kw.y
                   + qv[4 * d + 2] * kw.z + qv[4 * d + 3] * kw.w;
            }
            s *= 0.125f;
            if (kr0 + kk > qrow) s = -1e30f;
            Ss[kk][tid] = s;
            bm = fmaxf(bm, s);
        }

        float mnew = fmaxf(m, bm);
        float corr = __expf(m - mnew);
        l *= corr;
#pragma unroll
        for (int d = 0; d < 64; d++) acc[d] *= corr;

#pragma unroll 2
        for (int kk = 0; kk < 32; kk++) {
            float p = __expf(Ss[kk][tid] - mnew);
            l += p;
            const float4* vr = reinterpret_cast<const float4*>(&Vs[kk][0]);
#pragma unroll
            for (int d = 0; d < 16; d++) {
                float4 vw = vr[d];
                acc[4 * d]     += p * vw.x;
                acc[4 * d + 1] += p * vw.y;
                acc[4 * d + 2] += p * vw.z;
                acc[4 * d + 3] += p * vw.w;
            }
        }
        m = mnew;
    }

    float invl = 1.0f / l;
    float* op = O + ((size_t)(b * SEQ + qrow)) * DM + h * HD;
#pragma unroll
    for (int i = 0; i < 16; i++) {
        float4 t = make_float4(acc[4 * i] * invl, acc[4 * i + 1] * invl,
                               acc[4 * i + 2] * invl, acc[4 * i + 3] * invl);
        reinterpret_cast<float4*>(op)[i] = t;
    }
}

// ---------------- launch ----------------------------------------------------
extern "C" void kernel_launch(void* const* d_in, const int* in_sizes, int n_in,
                              void* d_out, int out_size) {
    const float* x  = (const float*)d_in[0];
    const float* Wq = (const float*)d_in[1];
    const float* Wk = (const float*)d_in[2];
    const float* Wv = (const float*)d_in[3];
    const float* Wo = (const float*)d_in[4];
    float* out = (float*)d_out;

    float *gq, *gk, *gv, *go;
    cudaGetSymbolAddress((void**)&gq, g_q);
    cudaGetSymbolAddress((void**)&gk, g_k);
    cudaGetSymbolAddress((void**)&gv, g_v);
    cudaGetSymbolAddress((void**)&go, g_o);

    static bool attr_set = false;
    if (!attr_set) {
        cudaFuncSetAttribute(gemm_tf32, cudaFuncAttributeMaxDynamicSharedMemorySize, GEMM_SMEM);
        attr_set = true;
    }

    // projections (tf32 mma.sync): q = x Wq^T, k = x Wk^T, v = x Wv^T
    gemm_tf32<<<dim3(DM / 128, NT / 128), 256, GEMM_SMEM>>>(x, Wq, gq, DM, DM);
    gemm_tf32<<<dim3((NKV * HD) / 128, NT / 128), 256, GEMM_SMEM>>>(x, Wk, gk, NKV * HD, DM);
    gemm_tf32<<<dim3((NKV * HD) / 128, NT / 128), 256, GEMM_SMEM>>>(x, Wv, gv, NKV * HD, DM);

    // RoPE on q and k
    int tq = NT * NH * 32;
    rope_kernel<<<(tq + 255) / 256, 256>>>(gq, NH, tq);
    int tk = NT * NKV * 32;
    rope_kernel<<<(tk + 255) / 256, 256>>>(gk, NKV, tk);

    // causal GQA attention (fp32)
    attn_kernel<<<dim3(SEQ / 64, B_SZ * NH), 64>>>(gq, gk, gv, go);

    // output projection into d_out
    gemm_tf32<<<dim3(DM / 128, NT / 128), 256, GEMM_SMEM>>>(go, Wo, out, DM, DM);
}

// round 7
// speedup vs baseline: 5.6019x; 1.9479x over previous
#include <cuda_runtime.h>
#include <cstdint>

#define B_SZ   2
#define SEQ    2048
#define DM     2048
#define NH     32
#define NKV    8
#define HD     64
#define NT     (B_SZ * SEQ)   // 4096 tokens

// ---------------- scratch (static device globals; no runtime allocation) ----
__device__ float g_q[(size_t)NT * DM];          // 32 MB
__device__ float g_k[(size_t)NT * NKV * HD];    //  8 MB
__device__ float g_v[(size_t)NT * NKV * HD];    //  8 MB
__device__ float g_o[(size_t)NT * DM];          // 32 MB

__device__ __forceinline__ float to_tf32(float x) {
    asm("cvt.rna.tf32.f32 %0, %1;" : "=f"(x) : "f"(x));
    return x;
}

#define MMA_TF32(c, a, b0_, b1_) \
    asm volatile("mma.sync.aligned.m16n8k8.row.col.f32.tf32.tf32.f32 " \
                 "{%0,%1,%2,%3}, {%4,%5,%6,%7}, {%8,%9}, {%0,%1,%2,%3};" \
                 : "+f"((c)[0]), "+f"((c)[1]), "+f"((c)[2]), "+f"((c)[3]) \
                 : "r"((a)[0]), "r"((a)[1]), "r"((a)[2]), "r"((a)[3]), \
                   "r"(b0_), "r"(b1_))

// ============ tf32 tensor GEMM: C[M,N] = A[M,K] * B[N,K]^T (row-major) ======
#define BK 32
#define LDS_PAD 36
#define TILE_F (128 * LDS_PAD)
#define GEMM_SMEM (4 * TILE_F * 4)

__global__ void __launch_bounds__(256, 1)
gemm_tf32(const float* __restrict__ A, const float* __restrict__ Bm,
          float* __restrict__ C, int N, int K) {
    extern __shared__ float smem[];
    const int tid = threadIdx.x;
    const int wid = tid >> 5;
    const int lane = tid & 31;
    const int g   = lane >> 2;
    const int tig = lane & 3;
    const int wm0 = (wid & 3) * 32;
    const int wn0 = (wid >> 2) * 64;
    const int n0 = blockIdx.x * 128;
    const int m0 = blockIdx.y * 128;

    const int lr = tid >> 3;
    const int lc = (tid & 7) * 4;

    float acc[2][8][4];
#pragma unroll
    for (int mt = 0; mt < 2; mt++)
#pragma unroll
        for (int nt = 0; nt < 8; nt++)
#pragma unroll
            for (int r = 0; r < 4; r++) acc[mt][nt][r] = 0.f;

    const int NITER = K / BK;
    float4 pa[4], pb[4];

#pragma unroll
    for (int t = 0; t < 4; t++) {
        int r = lr + t * 32;
        pa[t] = *reinterpret_cast<const float4*>(A  + (size_t)(m0 + r) * K + lc);
        pb[t] = *reinterpret_cast<const float4*>(Bm + (size_t)(n0 + r) * K + lc);
    }
    {
        float* As = smem;
        float* Bs = smem + TILE_F;
#pragma unroll
        for (int t = 0; t < 4; t++) {
            int r = lr + t * 32;
            float4 a = pa[t], b = pb[t];
            a.x = to_tf32(a.x); a.y = to_tf32(a.y); a.z = to_tf32(a.z); a.w = to_tf32(a.w);
            b.x = to_tf32(b.x); b.y = to_tf32(b.y); b.z = to_tf32(b.z); b.w = to_tf32(b.w);
            *reinterpret_cast<float4*>(&As[r * LDS_PAD + lc]) = a;
            *reinterpret_cast<float4*>(&Bs[r * LDS_PAD + lc]) = b;
        }
    }
    __syncthreads();

    for (int i = 0; i < NITER; i++) {
        if (i + 1 < NITER) {
            const int k0 = (i + 1) * BK;
#pragma unroll
            for (int t = 0; t < 4; t++) {
                int r = lr + t * 32;
                pa[t] = *reinterpret_cast<const float4*>(A  + (size_t)(m0 + r) * K + k0 + lc);
                pb[t] = *reinterpret_cast<const float4*>(Bm + (size_t)(n0 + r) * K + k0 + lc);
            }
        }

        const float* As = smem + (i & 1) * 2 * TILE_F;
        const float* Bs = As + TILE_F;
#pragma unroll
        for (int ks = 0; ks < 4; ks++) {
            const int k = ks * 8;
            uint32_t af[2][4], bf[8][2];
#pragma unroll
            for (int mt = 0; mt < 2; mt++) {
                const int am = wm0 + mt * 16 + g;
                af[mt][0] = __float_as_uint(As[(am)     * LDS_PAD + k + tig]);
                af[mt][1] = __float_as_uint(As[(am + 8) * LDS_PAD + k + tig]);
                af[mt][2] = __float_as_uint(As[(am)     * LDS_PAD + k + tig + 4]);
                af[mt][3] = __float_as_uint(As[(am + 8) * LDS_PAD + k + tig + 4]);
            }
#pragma unroll
            for (int nt = 0; nt < 8; nt++) {
                const int bn = wn0 + nt * 8 + g;
                bf[nt][0] = __float_as_uint(Bs[bn * LDS_PAD + k + tig]);
                bf[nt][1] = __float_as_uint(Bs[bn * LDS_PAD + k + tig + 4]);
            }
#pragma unroll
            for (int mt = 0; mt < 2; mt++)
#pragma unroll
                for (int nt = 0; nt < 8; nt++)
                    MMA_TF32(acc[mt][nt], af[mt], bf[nt][0], bf[nt][1]);
        }

        if (i + 1 < NITER) {
            float* Asn = smem + ((i + 1) & 1) * 2 * TILE_F;
            float* Bsn = Asn + TILE_F;
#pragma unroll
            for (int t = 0; t < 4; t++) {
                int r = lr + t * 32;
                float4 a = pa[t], b = pb[t];
                a.x = to_tf32(a.x); a.y = to_tf32(a.y); a.z = to_tf32(a.z); a.w = to_tf32(a.w);
                b.x = to_tf32(b.x); b.y = to_tf32(b.y); b.z = to_tf32(b.z); b.w = to_tf32(b.w);
                *reinterpret_cast<float4*>(&Asn[r * LDS_PAD + lc]) = a;
                *reinterpret_cast<float4*>(&Bsn[r * LDS_PAD + lc]) = b;
            }
            __syncthreads();
        }
    }

#pragma unroll
    for (int mt = 0; mt < 2; mt++) {
        const int row = m0 + wm0 + mt * 16 + g;
#pragma unroll
        for (int nt = 0; nt < 8; nt++) {
            const int col = n0 + wn0 + nt * 8 + tig * 2;
            const float* c = acc[mt][nt];
            *reinterpret_cast<float2*>(C + (size_t)row * N + col) = make_float2(c[0], c[1]);
            *reinterpret_cast<float2*>(C + (size_t)(row + 8) * N + col) = make_float2(c[2], c[3]);
        }
    }
}

// ---------------- RoPE (in place) -------------------------------------------
__global__ void rope_kernel(float* __restrict__ buf, int nheads, int total) {
    int idx = blockIdx.x * blockDim.x + threadIdx.x;
    if (idx >= total) return;
    int d   = idx & 31;
    int h   = (idx >> 5) % nheads;
    int row = idx / (32 * nheads);
    int s   = row & (SEQ - 1);
    float inv = expf(-(float)d * (9.210340371976184f / 32.0f));
    float ang = (float)s * inv;
    float c  = cosf(ang);
    float si = sinf(ang);
    float* p = buf + (size_t)row * (nheads * HD) + h * HD;
    float x1 = p[d];
    float x2 = p[d + 32];
    p[d]      = x1 * c - x2 * si;
    p[d + 32] = x2 * c + x1 * si;
}

// ======== causal GQA flash attention via mma.sync tf32 =======================
// Block: 128 threads (4 warps), 64 q-rows for one (b,h). Key tiles of 64.
// Warp w owns q-rows [w*16, w*16+16). S = QK^T with 3xTF32 split (hi/lo);
// softmax in c-frag registers; P -> warp-private smem -> a-frags; O += P*V.
#define APAD 68
#define ATTN_SMEM (4 * 64 * APAD * 4)   // Khi, Klo, Vs, Ps = 69632 B

__global__ void __launch_bounds__(128)
attn_mma(const float* __restrict__ Q, const float* __restrict__ K,
         const float* __restrict__ V, float* __restrict__ O) {
    extern __shared__ float sm[];
    float* Khi = sm;
    float* Klo = sm + 64 * APAD;
    float* Vs  = sm + 2 * 64 * APAD;
    float* Ps  = sm + 3 * 64 * APAD;

    const int qb = blockIdx.x;
    const int bh = blockIdx.y;
    const int b   = bh >> 5;
    const int h   = bh & 31;
    const int kvh = h >> 2;
    const int tid = threadIdx.x;
    const int wid = tid >> 5;
    const int lane = tid & 31;
    const int g   = lane >> 2;
    const int tig = lane & 3;
    const int q0 = qb * 64;
    const int wr = wid * 16;

    // ---- stage Q tile (64 rows x 16 float4) into Ps, then pull a-frags ----
#pragma unroll
    for (int t = 0; t < 8; t++) {
        int e = tid + t * 128;          // 0..1023
        int r = e >> 4;                 // 0..63
        int c = (e & 15) * 4;           // 0..60
        float4 v = *reinterpret_cast<const float4*>(
            Q + (size_t)(b * SEQ + q0 + r) * DM + h * HD + c);
        *reinterpret_cast<float4*>(&Ps[r * APAD + c]) = v;
    }
    __syncthreads();
    uint32_t qhi[8][4], qlo[8][4];
#pragma unroll
    for (int ks = 0; ks < 8; ks++) {
        const int r0 = wr + g, r1 = wr + g + 8;
        const int c0 = ks * 8 + tig, c1 = c0 + 4;
        float x, hi;
        x = Ps[r0 * APAD + c0]; hi = to_tf32(x);
        qhi[ks][0] = __float_as_uint(hi); qlo[ks][0] = __float_as_uint(to_tf32(x - hi));
        x = Ps[r1 * APAD + c0]; hi = to_tf32(x);
        qhi[ks][1] = __float_as_uint(hi); qlo[ks][1] = __float_as_uint(to_tf32(x - hi));
        x = Ps[r0 * APAD + c1]; hi = to_tf32(x);
        qhi[ks][2] = __float_as_uint(hi); qlo[ks][2] = __float_as_uint(to_tf32(x - hi));
        x = Ps[r1 * APAD + c1]; hi = to_tf32(x);
        qhi[ks][3] = __float_as_uint(hi); qlo[ks][3] = __float_as_uint(to_tf32(x - hi));
    }
    __syncthreads();

    float oc[8][4];
#pragma unroll
    for (int nt = 0; nt < 8; nt++)
#pragma unroll
        for (int r = 0; r < 4; r++) oc[nt][r] = 0.f;
    float mrow0 = -1e30f, mrow1 = -1e30f, lrow0 = 0.f, lrow1 = 0.f;

    for (int kt = 0; kt <= qb; kt++) {
        __syncthreads();   // prior PV reads of Vs done before overwrite
        // ---- load K (hi/lo) and V tiles: 64 rows x 16 float4 ----
#pragma unroll
        for (int t = 0; t < 8; t++) {
            int e = tid + t * 128;      // 0..1023
            int r = e >> 4;             // 0..63
            int c = (e & 15) * 4;
            size_t go = (size_t)(b * SEQ + kt * 64 + r) * (NKV * HD) + kvh * HD + c;
            float4 kv = *reinterpret_cast<const float4*>(K + go);
            float4 hi, lo;
            hi.x = to_tf32(kv.x); lo.x = to_tf32(kv.x - hi.x);
            hi.y = to_tf32(kv.y); lo.y = to_tf32(kv.y - hi.y);
            hi.z = to_tf32(kv.z); lo.z = to_tf32(kv.z - hi.z);
            hi.w = to_tf32(kv.w); lo.w = to_tf32(kv.w - hi.w);
            *reinterpret_cast<float4*>(&Khi[r * APAD + c]) = hi;
            *reinterpret_cast<float4*>(&Klo[r * APAD + c]) = lo;
            float4 vv = *reinterpret_cast<const float4*>(V + go);
            vv.x = to_tf32(vv.x); vv.y = to_tf32(vv.y);
            vv.z = to_tf32(vv.z); vv.w = to_tf32(vv.w);
            *reinterpret_cast<float4*>(&Vs[r * APAD + c]) = vv;
        }
        __syncthreads();

        // ---- S = Q K^T (3xTF32) ----
        float sc[8][4];
#pragma unroll
        for (int nt = 0; nt < 8; nt++)
#pragma unroll
            for (int r = 0; r < 4; r++) sc[nt][r] = 0.f;
#pragma unroll
        for (int ks = 0; ks < 8; ks++) {
#pragma unroll
            for (int nt = 0; nt < 8; nt++) {
                const int key = nt * 8 + g;
                uint32_t bh0 = __float_as_uint(Khi[key * APAD + ks * 8 + tig]);
                uint32_t bh1 = __float_as_uint(Khi[key * APAD + ks * 8 + tig + 4]);
                uint32_t bl0 = __float_as_uint(Klo[key * APAD + ks * 8 + tig]);
                uint32_t bl1 = __float_as_uint(Klo[key * APAD + ks * 8 + tig + 4]);
                MMA_TF32(sc[nt], qhi[ks], bh0, bh1);
                MMA_TF32(sc[nt], qhi[ks], bl0, bl1);
                MMA_TF32(sc[nt], qlo[ks], bh0, bh1);
            }
        }

        // ---- scale + causal mask + row max ----
        const bool diag = (kt == qb);
        const int row0 = wr + g, row1 = row0 + 8;
        float rm0 = -1e30f, rm1 = -1e30f;
#pragma unroll
        for (int nt = 0; nt < 8; nt++) {
            const int col0 = nt * 8 + tig * 2, col1 = col0 + 1;
            float s0 = sc[nt][0] * 0.125f; if (diag && col0 > row0) s0 = -1e30f;
            float s1 = sc[nt][1] * 0.125f; if (diag && col1 > row0) s1 = -1e30f;
            float s2 = sc[nt][2] * 0.125f; if (diag && col0 > row1) s2 = -1e30f;
            float s3 = sc[nt][3] * 0.125f; if (diag && col1 > row1) s3 = -1e30f;
            sc[nt][0] = s0; sc[nt][1] = s1; sc[nt][2] = s2; sc[nt][3] = s3;
            rm0 = fmaxf(rm0, fmaxf(s0, s1));
            rm1 = fmaxf(rm1, fmaxf(s2, s3));
        }
        rm0 = fmaxf(rm0, __shfl_xor_sync(0xFFFFFFFFu, rm0, 1));
        rm0 = fmaxf(rm0, __shfl_xor_sync(0xFFFFFFFFu, rm0, 2));
        rm1 = fmaxf(rm1, __shfl_xor_sync(0xFFFFFFFFu, rm1, 1));
        rm1 = fmaxf(rm1, __shfl_xor_sync(0xFFFFFFFFu, rm1, 2));

        const float mn0 = fmaxf(mrow0, rm0), mn1 = fmaxf(mrow1, rm1);
        const float corr0 = __expf(mrow0 - mn0), corr1 = __expf(mrow1 - mn1);
        mrow0 = mn0; mrow1 = mn1;

        // ---- P = exp(S - m), rescale O, stash P (warp-private rows) ----
        float rs0 = 0.f, rs1 = 0.f;
#pragma unroll
        for (int nt = 0; nt < 8; nt++) {
            float p0 = __expf(sc[nt][0] - mn0);
            float p1 = __expf(sc[nt][1] - mn0);
            float p2 = __expf(sc[nt][2] - mn1);
            float p3 = __expf(sc[nt][3] - mn1);
            rs0 += p0 + p1; rs1 += p2 + p3;
            oc[nt][0] *= corr0; oc[nt][1] *= corr0;
            oc[nt][2] *= corr1; oc[nt][3] *= corr1;
            *reinterpret_cast<float2*>(&Ps[row0 * APAD + nt * 8 + tig * 2]) =
                make_float2(to_tf32(p0), to_tf32(p1));
            *reinterpret_cast<float2*>(&Ps[row1 * APAD + nt * 8 + tig * 2]) =
                make_float2(to_tf32(p2), to_tf32(p3));
        }
        rs0 += __shfl_xor_sync(0xFFFFFFFFu, rs0, 1);
        rs0 += __shfl_xor_sync(0xFFFFFFFFu, rs0, 2);
        rs1 += __shfl_xor_sync(0xFFFFFFFFu, rs1, 1);
        rs1 += __shfl_xor_sync(0xFFFFFFFFu, rs1, 2);
        lrow0 = lrow0 * corr0 + rs0;
        lrow1 = lrow1 * corr1 + rs1;
        __syncwarp();

        // ---- O += P V ----
#pragma unroll
        for (int ks = 0; ks < 8; ks++) {
            uint32_t pa[4];
            pa[0] = __float_as_uint(Ps[row0 * APAD + ks * 8 + tig]);
            pa[1] = __float_as_uint(Ps[row1 * APAD + ks * 8 + tig]);
            pa[2] = __float_as_uint(Ps[row0 * APAD + ks * 8 + tig + 4]);
            pa[3] = __float_as_uint(Ps[row1 * APAD + ks * 8 + tig + 4]);
#pragma unroll
            for (int nt = 0; nt < 8; nt++) {
                uint32_t b0 = __float_as_uint(Vs[(ks * 8 + tig) * APAD + nt * 8 + g]);
                uint32_t b1 = __float_as_uint(Vs[(ks * 8 + tig + 4) * APAD + nt * 8 + g]);
                MMA_TF32(oc[nt], pa, b0, b1);
            }
        }
        __syncwarp();   // Ps reads done before next tile's stores
    }

    // ---- finalize ----
    const float inv0 = 1.0f / lrow0, inv1 = 1.0f / lrow1;
    const size_t gr0 = (size_t)(b * SEQ + q0 + wr + g);
#pragma unroll
    for (int nt = 0; nt < 8; nt++) {
        const int col = h * HD + nt * 8 + tig * 2;
        *reinterpret_cast<float2*>(O + gr0 * DM + col) =
            make_float2(oc[nt][0] * inv0, oc[nt][1] * inv0);
        *reinterpret_cast<float2*>(O + (gr0 + 8) * DM + col) =
            make_float2(oc[nt][2] * inv1, oc[nt][3] * inv1);
    }
}

// ---------------- launch ----------------------------------------------------
extern "C" void kernel_launch(void* const* d_in, const int* in_sizes, int n_in,
                              void* d_out, int out_size) {
    const float* x  = (const float*)d_in[0];
    const float* Wq = (const float*)d_in[1];
    const float* Wk = (const float*)d_in[2];
    const float* Wv = (const float*)d_in[3];
    const float* Wo = (const float*)d_in[4];
    float* out = (float*)d_out;

    float *gq, *gk, *gv, *go;
    cudaGetSymbolAddress((void**)&gq, g_q);
    cudaGetSymbolAddress((void**)&gk, g_k);
    cudaGetSymbolAddress((void**)&gv, g_v);
    cudaGetSymbolAddress((void**)&go, g_o);

    static bool attr_set = false;
    if (!attr_set) {
        cudaFuncSetAttribute(gemm_tf32, cudaFuncAttributeMaxDynamicSharedMemorySize, GEMM_SMEM);
        cudaFuncSetAttribute(attn_mma, cudaFuncAttributeMaxDynamicSharedMemorySize, ATTN_SMEM);
        attr_set = true;
    }

    // projections (tf32 mma.sync): q = x Wq^T, k = x Wk^T, v = x Wv^T
    gemm_tf32<<<dim3(DM / 128, NT / 128), 256, GEMM_SMEM>>>(x, Wq, gq, DM, DM);
    gemm_tf32<<<dim3((NKV * HD) / 128, NT / 128), 256, GEMM_SMEM>>>(x, Wk, gk, NKV * HD, DM);
    gemm_tf32<<<dim3((NKV * HD) / 128, NT / 128), 256, GEMM_SMEM>>>(x, Wv, gv, NKV * HD, DM);

    // RoPE on q and k
    int tq = NT * NH * 32;
    rope_kernel<<<(tq + 255) / 256, 256>>>(gq, NH, tq);
    int tk = NT * NKV * 32;
    rope_kernel<<<(tk + 255) / 256, 256>>>(gk, NKV, tk);

    // causal GQA attention (tf32 mma flash)
    attn_mma<<<dim3(SEQ / 64, B_SZ * NH), 128, ATTN_SMEM>>>(gq, gk, gv, go);

    // output projection into d_out
    gemm_tf32<<<dim3(DM / 128, NT / 128), 256, GEMM_SMEM>>>(go, Wo, out, DM, DM);
}